// round 13
// baseline (speedup 1.0000x reference)
#include <cuda_runtime.h>
#include <cuda_fp16.h>
#include <cstdint>

#define NS 16
#define CT 256
#define TAPS 64
#define UPAIR 32
#define PLANE 3969
#define PPAD 4096
#define MT 128
#define TSTRIDE 127
#define PTILES 32
#define MOUT 56
#define OUTN (MOUT * MOUT)

#define SM_A 0
#define SM_B 65536
#define SM_XB 98304                 // 8 warps x 32 floats exchange buffer
#define SMEM_TOTAL (SM_XB + 1024)

__device__ __align__(256) __half g_Dt[(size_t)NS * UPAIR * PPAD]; // 4.2 MB, [n][u][pos]

__device__ __forceinline__ float fast_sqrt(float v) {
    float r; asm("sqrt.approx.f32 %0, %1;" : "=f"(r) : "f"(v)); return r;
}
__device__ __forceinline__ uint32_t swz(int m, int cb) {
    return (uint32_t)(m * 512 + (cb ^ ((m & 7) << 4)));
}
__device__ __forceinline__ void ldsm_x4(uint32_t* r, uint32_t addr) {
    asm volatile("ldmatrix.sync.aligned.m8n8.x4.shared.b16 {%0,%1,%2,%3}, [%4];"
                 : "=r"(r[0]), "=r"(r[1]), "=r"(r[2]), "=r"(r[3]) : "r"(addr));
}
__device__ __forceinline__ void mma16816(float* d, const uint32_t* a, const uint32_t* b) {
    asm volatile("mma.sync.aligned.m16n8k16.row.col.f32.f16.f16.f32 "
                 "{%0,%1,%2,%3}, {%4,%5,%6,%7}, {%8,%9}, {%0,%1,%2,%3};"
                 : "+f"(d[0]), "+f"(d[1]), "+f"(d[2]), "+f"(d[3])
                 : "r"(a[0]), "r"(a[1]), "r"(a[2]), "r"(a[3]), "r"(b[0]), "r"(b[1]));
}

__global__ __launch_bounds__(256, 2)
void gemm_kernel(const float* __restrict__ z, const float* __restrict__ x,
                 const float* __restrict__ w)
{
    extern __shared__ char smem[];
    const uint32_t sb = (uint32_t)__cvta_generic_to_shared(smem);
    const int tid = threadIdx.x, wid = tid >> 5, lid = tid & 31;
    const int n = blockIdx.x, tile = blockIdx.y;
    const int pos0 = tile * TSTRIDE;         // tiles overlap by 1 column

    const float* xn = x + (size_t)n * CT * PLANE;
    const float* zn = z + (size_t)n * CT * TAPS;

    // ---- stage A = f16(sqrt(x)) : 128 pos x 256 ch (OOB -> 0) ----
    #pragma unroll 8
    for (int it = 0; it < 64; it++) {
        int pidx = it * 256 + tid;
        int m = pidx & 127, c0 = (pidx >> 7) * 2;
        bool ok = (pos0 + m) < PLANE;
        float f0 = ok ? fast_sqrt(xn[(size_t)c0 * PLANE + pos0 + m]) : 0.0f;
        float f1 = ok ? fast_sqrt(xn[(size_t)(c0 + 1) * PLANE + pos0 + m]) : 0.0f;
        uint32_t v; asm("cvt.rn.f16x2.f32 %0, %1, %2;" : "=r"(v) : "f"(f1), "f"(f0));
        asm volatile("st.shared.b32 [%0], %1;"
                     :: "r"(sb + SM_A + swz(m, c0 * 2)), "r"(v));
    }
    // ---- stage B = f16(w*sqrt(z)) : 64 taps x 256 ch ----
    #pragma unroll 8
    for (int it = 0; it < 32; it++) {
        int pidx = it * 256 + tid;
        int t = pidx & 63, c0 = (pidx >> 6) * 2;
        float f0 = w[c0]     * fast_sqrt(zn[(size_t)c0 * TAPS + t]);
        float f1 = w[c0 + 1] * fast_sqrt(zn[(size_t)(c0 + 1) * TAPS + t]);
        uint32_t v; asm("cvt.rn.f16x2.f32 %0, %1, %2;" : "=r"(v) : "f"(f1), "f"(f0));
        asm volatile("st.shared.b32 [%0], %1;"
                     :: "r"(sb + SM_B + swz(t, c0 * 2)), "r"(v));
    }
    __syncthreads();

    // ---- mainloop: each warp computes D[m_base..+15][0..63] ----
    const int m_base = wid * 16;
    float acc[8][4];
    #pragma unroll
    for (int nb = 0; nb < 8; nb++)
        #pragma unroll
        for (int e = 0; e < 4; e++) acc[nb][e] = 0.0f;

    const int a_m  = m_base + ((lid >> 3) & 1) * 8 + (lid & 7);
    const int a_cs = ((lid >> 4) & 1) * 16;
    const int b_t8 = ((lid >> 4) & 1) * 8 + (lid & 7);
    const int b_cs = ((lid >> 3) & 1) * 16;

    #pragma unroll
    for (int ks = 0; ks < 16; ks++) {
        uint32_t a[4];
        ldsm_x4(a, sb + SM_A + swz(a_m, ks * 32 + a_cs));
        #pragma unroll
        for (int jp = 0; jp < 4; jp++) {
            uint32_t b[4];
            int bt = jp * 16 + b_t8;
            ldsm_x4(b, sb + SM_B + swz(bt, ks * 32 + b_cs));
            mma16816(acc[2 * jp],     a, b);
            mma16816(acc[2 * jp + 1], a, b + 2);
        }
    }

    // Register layout reminder (t0 = nb*8 + 2*(lid&3), mr = m_base + (lid>>2)):
    //   acc[nb][0] = D[t0][mr],    acc[nb][1] = D[t0+1][mr]
    //   acc[nb][2] = D[t0][mr+8],  acc[nb][3] = D[t0+1][mr+8]

    // ---- cross-warp exchange: odd-tap D at column m_base of each warp ----
    float* xb = reinterpret_cast<float*>(smem + SM_XB);   // [8][32]
    if (lid < 4) {
        #pragma unroll
        for (int nb = 0; nb < 8; nb++)
            xb[wid * 32 + nb * 4 + lid] = acc[nb][1];     // D[t0+1][m_base]
    }
    __syncthreads();

    // ---- paired writeback: Dtp[u][pos] = D[2u][pos] + D[2u+1][pos+1] ----
    __half* dst = g_Dt + (size_t)n * UPAIR * PPAD + pos0;
    const bool hi = (lid >> 2) == 7;
    const int u  = ((lid & 3)) * 1 + 0;   // combined with nb below
    const int c0col = m_base + (lid >> 2);
    #pragma unroll
    for (int nb = 0; nb < 8; nb++) {
        float n1  = __shfl_down_sync(0xFFFFFFFFu, acc[nb][1], 4); // D[t0+1][mr+1]
        float a3s = __shfl_sync(0xFFFFFFFFu, acc[nb][3], lid & 3); // D[t0+1][m_base+8]
        float n3  = __shfl_down_sync(0xFFFFFFFFu, acc[nb][3], 4); // D[t0+1][mr+9]
        float nxt = (wid < 7) ? xb[(wid + 1) * 32 + nb * 4 + (lid & 3)] : 0.0f;

        float P0 = acc[nb][0] + (hi ? a3s : n1);
        float P1 = acc[nb][2] + (hi ? nxt : n3);

        int uu = nb * 4 + (lid & 3);
        dst[(size_t)uu * PPAD + c0col] = __float2half_rn(P0);
        if (!(wid == 7 && hi))                       // mask exclusive col 127
            dst[(size_t)uu * PPAD + c0col + 8] = __float2half_rn(P1);
    }
}

// 4 threads per output, 8 pair-taps each; smem combine.
__global__ __launch_bounds__(256, 4)
void epilogue_kernel(float* __restrict__ out)
{
    __shared__ float red[256];
    const int tid = threadIdx.x;
    const int jj = tid & 63, grp = tid >> 6;
    const int idx = blockIdx.x * 64 + jj;        // 784 * 64 = 50176 exactly
    const int n = idx / OUTN, r = idx - n * OUTN;
    const int i = r / MOUT, j = r - i * MOUT;
    const __half* base = g_Dt + (size_t)n * UPAIR * PPAD + i * 63 + j;

    float v[8];
    #pragma unroll
    for (int k = 0; k < 8; k++) {
        int u = grp * 8 + k;
        int p = u >> 2, q = 2 * (u & 3);
        v[k] = __half2float(base[(size_t)u * PPAD + p * 63 + q]);
    }
    #pragma unroll
    for (int s = 4; s >= 1; s >>= 1)
        #pragma unroll
        for (int k = 0; k < s; k++)
            v[k] += v[k + s];

    red[tid] = v[0];
    __syncthreads();
    if (grp == 0)
        out[idx] = (red[tid] + red[tid + 64] + red[tid + 128] + red[tid + 192])
                   * (1.0f / 64.0f);
}

extern "C" void kernel_launch(void* const* d_in, const int* in_sizes, int n_in,
                              void* d_out, int out_size)
{
    const float* z = (const float*)d_in[0];   // (16,256,8,8)
    const float* x = (const float*)d_in[1];   // (16,256,63,63)
    const float* w = (const float*)d_in[2];   // (1,256,1,1,1)
    float* out = (float*)d_out;               // (16,1,56,56)

    cudaFuncSetAttribute(gemm_kernel,
                         cudaFuncAttributeMaxDynamicSharedMemorySize, SMEM_TOTAL);
    dim3 grid(NS, PTILES);
    gemm_kernel<<<grid, 256, SMEM_TOTAL>>>(z, x, w);
    epilogue_kernel<<<NS * OUTN / 64, 256>>>(out);
}

// round 14
// speedup vs baseline: 1.0697x; 1.0697x over previous
#include <cuda_runtime.h>
#include <cuda_fp16.h>
#include <cstdint>

#define NS 16
#define CT 256
#define CH 128               // channels per K-half
#define TAPS 64
#define PLANE 3969
#define PPAD 4096
#define MT 128
#define PTILES 32
#define MOUT 56
#define OUTN (MOUT * MOUT)

// smem: A-half 128 pos x 128 ch f16 (256B rows) = 32768 B; B-half 64 x 128 = 16384 B
#define SM_A 0
#define SM_B 32768
#define SMEM_TOTAL (32768 + 16384)

__device__ __half g_Dt[(size_t)NS * TAPS * PPAD];   // 8.4 MB scratch, [n][tap][pos]

__device__ __forceinline__ float fast_sqrt(float v) {
    float r; asm("sqrt.approx.f32 %0, %1;" : "=f"(r) : "f"(v)); return r;
}
// 256B-row swizzle: 8 rows of an atom get distinct 16B offsets
__device__ __forceinline__ uint32_t swz(int m, int cb) {
    return (uint32_t)(m * 256 + (cb ^ ((m & 7) << 4)));
}
__device__ __forceinline__ void ldsm_x4(uint32_t* r, uint32_t addr) {
    asm volatile("ldmatrix.sync.aligned.m8n8.x4.shared.b16 {%0,%1,%2,%3}, [%4];"
                 : "=r"(r[0]), "=r"(r[1]), "=r"(r[2]), "=r"(r[3]) : "r"(addr));
}
__device__ __forceinline__ void mma16816(float* d, const uint32_t* a, const uint32_t* b) {
    asm volatile("mma.sync.aligned.m16n8k16.row.col.f32.f16.f16.f32 "
                 "{%0,%1,%2,%3}, {%4,%5,%6,%7}, {%8,%9}, {%0,%1,%2,%3};"
                 : "+f"(d[0]), "+f"(d[1]), "+f"(d[2]), "+f"(d[3])
                 : "r"(a[0]), "r"(a[1]), "r"(a[2]), "r"(a[3]), "r"(b[0]), "r"(b[1]));
}

__global__ __launch_bounds__(256, 3)
void gemm_kernel(const float* __restrict__ z, const float* __restrict__ x,
                 const float* __restrict__ w)
{
    extern __shared__ char smem[];
    const uint32_t sb = (uint32_t)__cvta_generic_to_shared(smem);
    const int tid = threadIdx.x, wid = tid >> 5, lid = tid & 31;
    const int n = blockIdx.x, tile = blockIdx.y;
    const int pos0 = (tile == PTILES - 1) ? (PLANE - MT) : tile * MT;

    const float* xn = x + (size_t)n * CT * PLANE;
    const float* zn = z + (size_t)n * CT * TAPS;

    const int m_base = wid * 16;
    float acc[8][4];
    #pragma unroll
    for (int nb = 0; nb < 8; nb++)
        #pragma unroll
        for (int e = 0; e < 4; e++) acc[nb][e] = 0.0f;

    const int a_m  = m_base + ((lid >> 3) & 1) * 8 + (lid & 7);
    const int a_cs = ((lid >> 4) & 1) * 16;
    const int b_t8 = ((lid >> 4) & 1) * 8 + (lid & 7);
    const int b_cs = ((lid >> 3) & 1) * 16;

    #pragma unroll 1
    for (int half = 0; half < 2; half++) {
        const int cb = half * CH;              // global channel base of this half
        if (half) __syncthreads();             // previous mainloop done reading

        // ---- stage A-half = f16(sqrt(x)) : 128 pos x 128 ch ----
        #pragma unroll 8
        for (int it = 0; it < 32; it++) {
            int pidx = it * 256 + tid;         // 8192 channel-pair items
            int m = pidx & 127, c0 = (pidx >> 7) * 2;
            float f0 = fast_sqrt(xn[(size_t)(cb + c0) * PLANE + pos0 + m]);
            float f1 = fast_sqrt(xn[(size_t)(cb + c0 + 1) * PLANE + pos0 + m]);
            uint32_t v; asm("cvt.rn.f16x2.f32 %0, %1, %2;" : "=r"(v) : "f"(f1), "f"(f0));
            asm volatile("st.shared.b32 [%0], %1;"
                         :: "r"(sb + SM_A + swz(m, c0 * 2)), "r"(v));
        }
        // ---- stage B-half = f16(w*sqrt(z)) : 64 taps x 128 ch ----
        #pragma unroll 8
        for (int it = 0; it < 16; it++) {
            int pidx = it * 256 + tid;         // 4096 items
            int t = pidx & 63, c0 = (pidx >> 6) * 2;
            float f0 = w[cb + c0]     * fast_sqrt(zn[(size_t)(cb + c0) * TAPS + t]);
            float f1 = w[cb + c0 + 1] * fast_sqrt(zn[(size_t)(cb + c0 + 1) * TAPS + t]);
            uint32_t v; asm("cvt.rn.f16x2.f32 %0, %1, %2;" : "=r"(v) : "f"(f1), "f"(f0));
            asm volatile("st.shared.b32 [%0], %1;"
                         :: "r"(sb + SM_B + swz(t, c0 * 2)), "r"(v));
        }
        __syncthreads();

        // ---- mainloop over this half's 8 K-steps ----
        #pragma unroll
        for (int ks = 0; ks < 8; ks++) {
            uint32_t a[4];
            ldsm_x4(a, sb + SM_A + swz(a_m, ks * 32 + a_cs));
            #pragma unroll
            for (int jp = 0; jp < 4; jp++) {
                uint32_t b[4];
                int bt = jp * 16 + b_t8;
                ldsm_x4(b, sb + SM_B + swz(bt, ks * 32 + b_cs));
                mma16816(acc[2 * jp],     a, b);
                mma16816(acc[2 * jp + 1], a, b + 2);
            }
        }
    }

    // ---- writeback D -> g_Dt[n][tap][pos] as f16 (R11 layout, untouched) ----
    __half* dst = g_Dt + (size_t)n * TAPS * PPAD;
    const int mr = m_base + (lid >> 2);
    const int tc = 2 * (lid & 3);
    #pragma unroll
    for (int nb = 0; nb < 8; nb++) {
        int t0 = nb * 8 + tc;
        dst[(size_t)t0 * PPAD + pos0 + mr]           = __float2half_rn(acc[nb][0]);
        dst[(size_t)(t0 + 1) * PPAD + pos0 + mr]     = __float2half_rn(acc[nb][1]);
        dst[(size_t)t0 * PPAD + pos0 + mr + 8]       = __float2half_rn(acc[nb][2]);
        dst[(size_t)(t0 + 1) * PPAD + pos0 + mr + 8] = __float2half_rn(acc[nb][3]);
    }
}

// 4 threads per output, 16 taps each; smem combine. All loads scalar __half.
__global__ __launch_bounds__(256, 4)
void epilogue_kernel(float* __restrict__ out)
{
    __shared__ float red[256];
    const int tid = threadIdx.x;
    const int jj = tid & 63, grp = tid >> 6;
    const int idx = blockIdx.x * 64 + jj;        // 784 * 64 = 50176 exactly
    const int n = idx / OUTN, r = idx - n * OUTN;
    const int i = r / MOUT, j = r - i * MOUT;
    const __half* base = g_Dt + (size_t)n * TAPS * PPAD + i * 63 + j;

    float v[16];
    #pragma unroll
    for (int k = 0; k < 16; k++) {
        int t = grp * 16 + k;
        int p = t >> 3, q = t & 7;
        v[k] = __half2float(base[(size_t)t * PPAD + p * 63 + q]);
    }
    #pragma unroll
    for (int s = 8; s >= 1; s >>= 1)
        #pragma unroll
        for (int k = 0; k < s; k++)
            v[k] += v[k + s];

    red[tid] = v[0];
    __syncthreads();
    if (grp == 0)
        out[idx] = (red[tid] + red[tid + 64] + red[tid + 128] + red[tid + 192])
                   * (1.0f / 64.0f);
}

extern "C" void kernel_launch(void* const* d_in, const int* in_sizes, int n_in,
                              void* d_out, int out_size)
{
    const float* z = (const float*)d_in[0];   // (16,256,8,8)
    const float* x = (const float*)d_in[1];   // (16,256,63,63)
    const float* w = (const float*)d_in[2];   // (1,256,1,1,1)
    float* out = (float*)d_out;               // (16,1,56,56)

    cudaFuncSetAttribute(gemm_kernel,
                         cudaFuncAttributeMaxDynamicSharedMemorySize, SMEM_TOTAL);
    dim3 grid(NS, PTILES);
    gemm_kernel<<<grid, 256, SMEM_TOTAL>>>(z, x, w);
    epilogue_kernel<<<NS * OUTN / 64, 256>>>(out);
}

// round 15
// speedup vs baseline: 1.1475x; 1.0727x over previous
#include <cuda_runtime.h>
#include <cuda_fp16.h>
#include <cstdint>

#define NS 16
#define CT 256
#define TAPS 64
#define PLANE 3969
#define PPAD 4096
#define MT 128
#define PTILES 32
#define MOUT 56
#define OUTN (MOUT * MOUT)

#define SM_A 0
#define SM_B 65536
#define SMEM_TOTAL (65536 + 32768)

__device__ __half g_Dt[(size_t)NS * TAPS * PPAD];   // 8.4 MB scratch, [n][tap][pos]

__device__ __forceinline__ float fast_sqrt(float v) {
    float r; asm("sqrt.approx.f32 %0, %1;" : "=f"(r) : "f"(v)); return r;
}
__device__ __forceinline__ uint32_t swz(int m, int cb) {
    return (uint32_t)(m * 512 + (cb ^ ((m & 7) << 4)));
}
__device__ __forceinline__ void ldsm_x4(uint32_t* r, uint32_t addr) {
    asm volatile("ldmatrix.sync.aligned.m8n8.x4.shared.b16 {%0,%1,%2,%3}, [%4];"
                 : "=r"(r[0]), "=r"(r[1]), "=r"(r[2]), "=r"(r[3]) : "r"(addr));
}
__device__ __forceinline__ void mma16816(float* d, const uint32_t* a, const uint32_t* b) {
    asm volatile("mma.sync.aligned.m16n8k16.row.col.f32.f16.f16.f32 "
                 "{%0,%1,%2,%3}, {%4,%5,%6,%7}, {%8,%9}, {%0,%1,%2,%3};"
                 : "+f"(d[0]), "+f"(d[1]), "+f"(d[2]), "+f"(d[3])
                 : "r"(a[0]), "r"(a[1]), "r"(a[2]), "r"(a[3]), "r"(b[0]), "r"(b[1]));
}

__global__ __launch_bounds__(256, 2)
void gemm_kernel(const float* __restrict__ z, const float* __restrict__ x,
                 const float* __restrict__ w)
{
    extern __shared__ char smem[];
    const uint32_t sb = (uint32_t)__cvta_generic_to_shared(smem);
    const int tid = threadIdx.x, wid = tid >> 5, lid = tid & 31;
    const int tile = blockIdx.x, n = blockIdx.y;   // tile fastest: same-n CTAs adjacent
    const int pos0 = (tile == PTILES - 1) ? (PLANE - MT) : tile * MT;

    const float* xn = x + (size_t)n * CT * PLANE;
    const float* zn = z + (size_t)n * CT * TAPS;

    // ---- stage A = f16(sqrt(x)) : 128 pos x 256 ch ----
    #pragma unroll 16
    for (int it = 0; it < 64; it++) {
        int pidx = it * 256 + tid;
        int m = pidx & 127, c0 = (pidx >> 7) * 2;
        float f0 = fast_sqrt(xn[(size_t)c0 * PLANE + pos0 + m]);
        float f1 = fast_sqrt(xn[(size_t)(c0 + 1) * PLANE + pos0 + m]);
        uint32_t v; asm("cvt.rn.f16x2.f32 %0, %1, %2;" : "=r"(v) : "f"(f1), "f"(f0));
        asm volatile("st.shared.b32 [%0], %1;"
                     :: "r"(sb + SM_A + swz(m, c0 * 2)), "r"(v));
    }
    // ---- stage B = f16(w*sqrt(z)) : 64 taps x 256 ch ----
    #pragma unroll 8
    for (int it = 0; it < 32; it++) {
        int pidx = it * 256 + tid;
        int t = pidx & 63, c0 = (pidx >> 6) * 2;
        float f0 = w[c0]     * fast_sqrt(zn[(size_t)c0 * TAPS + t]);
        float f1 = w[c0 + 1] * fast_sqrt(zn[(size_t)(c0 + 1) * TAPS + t]);
        uint32_t v; asm("cvt.rn.f16x2.f32 %0, %1, %2;" : "=r"(v) : "f"(f1), "f"(f0));
        asm volatile("st.shared.b32 [%0], %1;"
                     :: "r"(sb + SM_B + swz(t, c0 * 2)), "r"(v));
    }
    __syncthreads();

    // ---- mainloop: each warp computes D[m_base..+15][0..63] ----
    const int m_base = wid * 16;
    float acc[8][4];
    #pragma unroll
    for (int nb = 0; nb < 8; nb++)
        #pragma unroll
        for (int e = 0; e < 4; e++) acc[nb][e] = 0.0f;

    const int a_m  = m_base + ((lid >> 3) & 1) * 8 + (lid & 7);
    const int a_cs = ((lid >> 4) & 1) * 16;
    const int b_t8 = ((lid >> 4) & 1) * 8 + (lid & 7);
    const int b_cs = ((lid >> 3) & 1) * 16;

    #pragma unroll
    for (int ks = 0; ks < 16; ks++) {
        uint32_t a[4];
        ldsm_x4(a, sb + SM_A + swz(a_m, ks * 32 + a_cs));
        #pragma unroll
        for (int jp = 0; jp < 4; jp++) {
            uint32_t b[4];
            int bt = jp * 16 + b_t8;
            ldsm_x4(b, sb + SM_B + swz(bt, ks * 32 + b_cs));
            mma16816(acc[2 * jp],     a, b);
            mma16816(acc[2 * jp + 1], a, b + 2);
        }
    }

    // ---- writeback D -> g_Dt[n][tap][pos] as f16 (R11 direct scatter) ----
    __half* dst = g_Dt + (size_t)n * TAPS * PPAD;
    const int mr = m_base + (lid >> 2);
    const int tc = 2 * (lid & 3);
    #pragma unroll
    for (int nb = 0; nb < 8; nb++) {
        int t0 = nb * 8 + tc;
        dst[(size_t)t0 * PPAD + pos0 + mr]           = __float2half_rn(acc[nb][0]);
        dst[(size_t)(t0 + 1) * PPAD + pos0 + mr]     = __float2half_rn(acc[nb][1]);
        dst[(size_t)t0 * PPAD + pos0 + mr + 8]       = __float2half_rn(acc[nb][2]);
        dst[(size_t)(t0 + 1) * PPAD + pos0 + mr + 8] = __float2half_rn(acc[nb][3]);
    }
}

// 8 threads per output, 8 taps each; smem tree combine. 32 outputs per CTA.
__global__ __launch_bounds__(256, 4)
void epilogue_kernel(float* __restrict__ out)
{
    __shared__ float red[256];
    const int tid = threadIdx.x;
    const int jj = tid & 31, grp = tid >> 5;
    const int idx = blockIdx.x * 32 + jj;        // 1568 * 32 = 50176 exactly
    const int n = idx / OUTN, r = idx - n * OUTN;
    const int i = r / MOUT, j = r - i * MOUT;
    const __half* base = g_Dt + (size_t)n * TAPS * PPAD + i * 63 + j;

    float v[8];
    #pragma unroll
    for (int k = 0; k < 8; k++) {
        int t = grp * 8 + k;
        int p = t >> 3, q = t & 7;
        v[k] = __half2float(base[(size_t)t * PPAD + p * 63 + q]);
    }
    #pragma unroll
    for (int s = 4; s >= 1; s >>= 1)
        #pragma unroll
        for (int k = 0; k < s; k++)
            v[k] += v[k + s];

    red[tid] = v[0];
    __syncthreads();
    if (tid < 128) red[tid] += red[tid + 128];
    __syncthreads();
    if (tid < 64)  red[tid] += red[tid + 64];
    __syncthreads();
    if (tid < 32)
        out[blockIdx.x * 32 + tid] = (red[tid] + red[tid + 32]) * (1.0f / 64.0f);
}

extern "C" void kernel_launch(void* const* d_in, const int* in_sizes, int n_in,
                              void* d_out, int out_size)
{
    const float* z = (const float*)d_in[0];   // (16,256,8,8)
    const float* x = (const float*)d_in[1];   // (16,256,63,63)
    const float* w = (const float*)d_in[2];   // (1,256,1,1,1)
    float* out = (float*)d_out;               // (16,1,56,56)

    cudaFuncSetAttribute(gemm_kernel,
                         cudaFuncAttributeMaxDynamicSharedMemorySize, SMEM_TOTAL);
    dim3 grid(PTILES, NS);
    gemm_kernel<<<grid, 256, SMEM_TOTAL>>>(z, x, w);
    epilogue_kernel<<<NS * OUTN / 32, 256>>>(out);
}